// round 15
// baseline (speedup 1.0000x reference)
#include <cuda_runtime.h>
#include <cuda_fp16.h>
#include <math.h>
#include <stdint.h>

#define Bdim 2
#define NHdim 4
#define Tdim 1024
#define Ndim 8192
#define Ddim 256
#define BHdim (Bdim * NHdim)

// Scratch (no cudaMalloc allowed)
static __device__ __half g_Qh[67108864];  // [BH, T, N] rope(Q) fp16, 128 MB
static __device__ __half g_Sh[8388608];   // [BH, T, T] scores fp16
static __device__ __half g_VTh[Bdim * Ddim * Tdim];  // [B, D, T] V^T fp16
static __device__ float g_gate[BHdim * Tdim];
static __device__ float g_S_fallback[8388608];

// ---------------------------------------------------------------------------
// PTX helpers
// ---------------------------------------------------------------------------
__device__ __forceinline__ uint32_t smem_u32(const void* p) {
    uint32_t a;
    asm("{ .reg .u64 t; cvta.to.shared.u64 t, %1; cvt.u32.u64 %0, t; }"
        : "=r"(a) : "l"(p));
    return a;
}
__device__ __forceinline__ void cp16(uint32_t s, const void* g) {
    asm volatile("cp.async.cg.shared.global [%0], [%1], 16;" :: "r"(s), "l"(g)
                 : "memory");
}
__device__ __forceinline__ void ldm_x4(uint32_t* r, uint32_t addr) {
    asm volatile(
        "ldmatrix.sync.aligned.m8n8.x4.shared.b16 {%0,%1,%2,%3}, [%4];"
        : "=r"(r[0]), "=r"(r[1]), "=r"(r[2]), "=r"(r[3]) : "r"(addr));
}
__device__ __forceinline__ void mma16816(float* c, const uint32_t* a,
                                         uint32_t b0, uint32_t b1) {
    asm volatile(
        "mma.sync.aligned.m16n8k16.row.col.f32.f16.f16.f32 "
        "{%0,%1,%2,%3}, {%4,%5,%6,%7}, {%8,%9}, {%0,%1,%2,%3};"
        : "+f"(c[0]), "+f"(c[1]), "+f"(c[2]), "+f"(c[3])
        : "r"(a[0]), "r"(a[1]), "r"(a[2]), "r"(a[3]), "r"(b0), "r"(b1));
}
__device__ __forceinline__ uint32_t swz(uint32_t off) {
    return off ^ ((off >> 3) & 0x70);  // SW128
}
__device__ __forceinline__ void mbar_init(uint32_t a, uint32_t cnt) {
    asm volatile("mbarrier.init.shared.b64 [%0], %1;" :: "r"(a), "r"(cnt)
                 : "memory");
}
__device__ __forceinline__ void mbar_wait(uint32_t a, uint32_t parity) {
    asm volatile(
        "{\n\t.reg .pred P;\n"
        "WL_%=:\n\t"
        "mbarrier.try_wait.parity.acquire.cta.shared::cta.b64 P, [%0], %1, 0x989680;\n\t"
        "@!P bra WL_%=;\n\t}"
        :: "r"(a), "r"(parity) : "memory");
}
__device__ __forceinline__ void mbar_arrive(uint32_t a) {
    asm volatile("mbarrier.arrive.shared.b64 _, [%0];" :: "r"(a) : "memory");
}
__device__ __forceinline__ void cp_arrive(uint32_t a) {
    asm volatile("cp.async.mbarrier.arrive.noinc.shared.b64 [%0];" :: "r"(a)
                 : "memory");
}

// ---------------------------------------------------------------------------
// RoPE -> fp16
// ---------------------------------------------------------------------------
__global__ void rope_kernel(const float* __restrict__ Q) {
    size_t idx = (size_t)blockIdx.x * blockDim.x + threadIdx.x;
    const size_t NQ = (size_t)BHdim * Tdim * (Ndim / 4);
    if (idx >= NQ) return;
    int p2 = (int)(idx % (Ndim / 4));
    int t = (int)((idx / (Ndim / 4)) % Tdim);
    float4 v = ((const float4*)Q)[idx];
    const float tf = (float)t;
    const float k = -16.0f * 2.0f / (float)Ndim;

    float fr0 = exp2f(k * (float)(2 * p2)) * 0.15915494309189535f;
    float ph0 = tf * fr0;
    ph0 = (ph0 - floorf(ph0)) * 6.283185307179586f;
    float s0, c0;
    __sincosf(ph0, &s0, &c0);

    float fr1 = exp2f(k * (float)(2 * p2 + 1)) * 0.15915494309189535f;
    float ph1 = tf * fr1;
    ph1 = (ph1 - floorf(ph1)) * 6.283185307179586f;
    float s1, c1;
    __sincosf(ph1, &s1, &c1);

    __half2 h0, h1;
    h0.x = __float2half(v.x * c0 - v.y * s0);
    h0.y = __float2half(v.y * c0 + v.x * s0);
    h1.x = __float2half(v.z * c1 - v.w * s1);
    h1.y = __float2half(v.w * c1 + v.z * s1);
    ((__half2*)g_Qh)[idx * 2 + 0] = h0;
    ((__half2*)g_Qh)[idx * 2 + 1] = h1;
}

// ---------------------------------------------------------------------------
// Gate
// ---------------------------------------------------------------------------
__global__ void gate_kernel(const float* __restrict__ traces) {
    int row = blockIdx.x;
    const float* pr = traces + (size_t)row * Ddim;
    float sum = 0.f;
    for (int i = threadIdx.x; i < Ddim; i += 32) sum += pr[i];
#pragma unroll
    for (int o = 16; o; o >>= 1) sum += __shfl_xor_sync(0xffffffffu, sum, o);
    if (threadIdx.x == 0) {
        float m = sum * (1.0f / (float)Ddim);
        float sig = 1.0f / (1.0f + expf(-m));
        g_gate[row] = 0.5f + 0.5f * sig;
    }
}

// ---------------------------------------------------------------------------
// V transpose -> fp16: VT[b][d][s]
// ---------------------------------------------------------------------------
__global__ void vt_kernel(const float* __restrict__ V) {
    __shared__ float tile[32][33];
    const int b = blockIdx.z;
    const int s0 = blockIdx.x * 32, d0 = blockIdx.y * 32;
#pragma unroll
    for (int j = 0; j < 4; j++)
        tile[threadIdx.y + 8 * j][threadIdx.x] =
            V[(size_t)b * Tdim * Ddim + (size_t)(s0 + threadIdx.y + 8 * j) * Ddim +
              d0 + threadIdx.x];
    __syncthreads();
#pragma unroll
    for (int j = 0; j < 4; j++) {
        int d = d0 + threadIdx.y + 8 * j;
        int s = s0 + threadIdx.x;
        float v = tile[threadIdx.x][threadIdx.y + 8 * j];
        g_VTh[(size_t)b * Ddim * Tdim + (size_t)d * Tdim + s] = __float2half(v);
    }
}

// ---------------------------------------------------------------------------
// Zero-fill kernel for strictly-upper tiles (bt < bs).
// ---------------------------------------------------------------------------
__global__ void zero_upper_kernel(float* __restrict__ Sc) {
    const int bh = blockIdx.x & 7;
    int j = blockIdx.x >> 3;
    int c = (int)((sqrtf(8.f * (float)j + 1.f) + 1.f) * 0.5f);
    while (c * (c - 1) / 2 > j) c--;
    while ((c + 1) * c / 2 <= j) c++;
    const int bs = c;
    const int bt = j - c * (c - 1) / 2;
    float* Sbase = Sc + (size_t)bh * Tdim * Tdim;
    __half* Shb = g_Sh + (size_t)bh * Tdim * Tdim;
    const int r0 = bt * 128, c0 = bs * 128;
    float4 z = make_float4(0.f, 0.f, 0.f, 0.f);
    for (int i = threadIdx.x; i < 128 * 32; i += 256) {
        int r = i >> 5, cc = (i & 31) << 2;
        *(float4*)(Sbase + (size_t)(r0 + r) * Tdim + c0 + cc) = z;
    }
    for (int i = threadIdx.x; i < 128 * 16; i += 256) {
        int r = i >> 4, cc = (i & 15) << 3;
        *(uint4*)(Shb + (size_t)(r0 + r) * Tdim + c0 + cc) = make_uint4(0, 0, 0, 0);
    }
}

// ===========================================================================
// SCORES: unchanged round-14 mbarrier version.
// ===========================================================================
#define STG_SC 32768
#define MB_OFF (3 * STG_SC)
#define SMEM_SC (3 * STG_SC + 64)

struct Frag4 {
    uint32_t a_off[4];
    uint32_t b_off[4];
    uint32_t sw[8];
    uint32_t gof[8];
};

__device__ __forceinline__ void frag4_setup(Frag4& f, int tid, uint32_t rstride) {
    const int lid = tid & 31;
    const int wid = tid >> 5;
    const int wr = wid >> 1;
    const int wc = wid & 1;
    const int a_row = wr * 64 + (lid & 15);
    const int a_kb = (lid >> 4) * 16;
#pragma unroll
    for (int mi = 0; mi < 4; mi++)
        f.a_off[mi] = swz((a_row + mi * 16) * 128 + a_kb);
    const int b_row = wc * 64 + (lid & 7) + ((lid >> 4) << 3);
    const int b_kb = ((lid >> 3) & 1) * 16;
#pragma unroll
    for (int nb = 0; nb < 4; nb++)
        f.b_off[nb] = swz((b_row + nb * 16) * 128 + b_kb);
    const int rbase = tid >> 3;
    const int colb = (tid & 7) * 16;
#pragma unroll
    for (int r = 0; r < 8; r++) {
        int row = rbase + 16 * r;
        f.sw[r] = swz(row * 128 + colb);
        f.gof[r] = (uint32_t)row * rstride + colb;
    }
}

__device__ __forceinline__ void ks4_step(const Frag4& f, uint32_t asm_,
                                         uint32_t bsm, uint32_t kx,
                                         float acc[4][8][4]) {
    uint32_t b[4][4];
#pragma unroll
    for (int nb = 0; nb < 4; nb++) ldm_x4(b[nb], bsm + (f.b_off[nb] ^ kx));
    uint32_t a0[4], a1[4];
    ldm_x4(a0, asm_ + (f.a_off[0] ^ kx));
    ldm_x4(a1, asm_ + (f.a_off[1] ^ kx));
#pragma unroll
    for (int nb = 0; nb < 4; nb++) {
        mma16816(acc[0][2 * nb + 0], a0, b[nb][0], b[nb][1]);
        mma16816(acc[0][2 * nb + 1], a0, b[nb][2], b[nb][3]);
    }
    ldm_x4(a0, asm_ + (f.a_off[2] ^ kx));
#pragma unroll
    for (int nb = 0; nb < 4; nb++) {
        mma16816(acc[1][2 * nb + 0], a1, b[nb][0], b[nb][1]);
        mma16816(acc[1][2 * nb + 1], a1, b[nb][2], b[nb][3]);
    }
    ldm_x4(a1, asm_ + (f.a_off[3] ^ kx));
#pragma unroll
    for (int nb = 0; nb < 4; nb++) {
        mma16816(acc[2][2 * nb + 0], a0, b[nb][0], b[nb][1]);
        mma16816(acc[2][2 * nb + 1], a0, b[nb][2], b[nb][3]);
    }
#pragma unroll
    for (int nb = 0; nb < 4; nb++) {
        mma16816(acc[3][2 * nb + 0], a1, b[nb][0], b[nb][1]);
        mma16816(acc[3][2 * nb + 1], a1, b[nb][2], b[nb][3]);
    }
}

__global__ __launch_bounds__(128, 2) void scores_tc_kernel(
    float* __restrict__ Sc, const float* __restrict__ stdp_scale) {
    extern __shared__ char smem[];
    const int bh = blockIdx.x & 7;
    int kidx = blockIdx.x >> 3;
    int bt = (int)((sqrtf(8.f * (float)kidx + 1.f) - 1.f) * 0.5f);
    while (bt * (bt + 1) / 2 > kidx) bt--;
    while ((bt + 1) * (bt + 2) / 2 <= kidx) bt++;
    const int bs = kidx - bt * (bt + 1) / 2;

    float* Sbase = Sc + (size_t)bh * Tdim * Tdim;
    __half* Shb = g_Sh + (size_t)bh * Tdim * Tdim;

    const uint32_t sbase = smem_u32(smem);
    const int tid = threadIdx.x;
    const int wid = tid >> 5;
    const int lid = tid & 31;
    const int wr = wid >> 1;
    const int wc = wid & 1;

    const uint32_t MB = sbase + MB_OFF;
    if (tid == 0) {
#pragma unroll
        for (int s = 0; s < 3; s++) {
            mbar_init(MB + s * 8, 128);
            mbar_init(MB + 24 + s * 8, 4);
        }
    }
    __syncthreads();

    Frag4 f;
    frag4_setup(f, tid, (uint32_t)Ndim * 2);

    const char* Ab = (const char*)(g_Qh + ((size_t)bh * Tdim + bt * 128) * Ndim);
    const char* Bb = (const char*)(g_Qh + ((size_t)bh * Tdim + bs * 128) * Ndim);

    float acc[4][8][4];
#pragma unroll
    for (int i = 0; i < 4; i++)
#pragma unroll
        for (int j = 0; j < 8; j++)
#pragma unroll
            for (int k = 0; k < 4; k++) acc[i][j][k] = 0.f;

    const int NCH = 128;
#pragma unroll
    for (int c = 0; c < 2; c++) {
        uint32_t s0 = sbase + c * STG_SC;
        size_t kb = (size_t)c * 128;
#pragma unroll
        for (int r = 0; r < 8; r++) {
            cp16(s0 + f.sw[r],         Ab + f.gof[r] + kb);
            cp16(s0 + 16384 + f.sw[r], Bb + f.gof[r] + kb);
        }
        cp_arrive(MB + c * 8);
    }

    int s = 0, m = 0;
    for (int c = 0; c < NCH; c++) {
        mbar_wait(MB + s * 8, m & 1);
        const uint32_t s0 = sbase + s * STG_SC;
        ks4_step(f, s0, s0 + 16384, 0, acc);

        const int p = c + 2;
        if (p < NCH) {
            int sp = s + 2;
            if (sp >= 3) sp -= 3;
            const int pdiv = m + (s >= 1 ? 1 : 0);
            if (p >= 3) mbar_wait(MB + 24 + sp * 8, (pdiv - 1) & 1);
            const uint32_t spb = sbase + sp * STG_SC;
            const size_t kb = (size_t)p * 128;
            cp16(spb + f.sw[0],         Ab + f.gof[0] + kb);
            cp16(spb + f.sw[1],         Ab + f.gof[1] + kb);
            cp16(spb + f.sw[2],         Ab + f.gof[2] + kb);
            cp16(spb + 16384 + f.sw[0], Bb + f.gof[0] + kb);
            cp16(spb + 16384 + f.sw[1], Bb + f.gof[1] + kb);
            cp16(spb + 16384 + f.sw[2], Bb + f.gof[2] + kb);
            ks4_step(f, s0, s0 + 16384, 32, acc);
            cp16(spb + f.sw[3],         Ab + f.gof[3] + kb);
            cp16(spb + f.sw[4],         Ab + f.gof[4] + kb);
            cp16(spb + f.sw[5],         Ab + f.gof[5] + kb);
            cp16(spb + 16384 + f.sw[3], Bb + f.gof[3] + kb);
            cp16(spb + 16384 + f.sw[4], Bb + f.gof[4] + kb);
            cp16(spb + 16384 + f.sw[5], Bb + f.gof[5] + kb);
            ks4_step(f, s0, s0 + 16384, 64, acc);
            cp16(spb + f.sw[6],         Ab + f.gof[6] + kb);
            cp16(spb + f.sw[7],         Ab + f.gof[7] + kb);
            cp16(spb + 16384 + f.sw[6], Bb + f.gof[6] + kb);
            cp16(spb + 16384 + f.sw[7], Bb + f.gof[7] + kb);
            cp_arrive(MB + sp * 8);
            ks4_step(f, s0, s0 + 16384, 96, acc);
        } else {
            ks4_step(f, s0, s0 + 16384, 32, acc);
            ks4_step(f, s0, s0 + 16384, 64, acc);
            ks4_step(f, s0, s0 + 16384, 96, acc);
        }
        __syncwarp();
        if (lid == 0) mbar_arrive(MB + 24 + s * 8);
        if (++s == 3) { s = 0; m++; }
    }

    const float ssc = stdp_scale[0] * 0.01f;
    const int g0 = lid >> 2;
    const int tg = lid & 3;
#pragma unroll
    for (int mi = 0; mi < 4; mi++) {
#pragma unroll
        for (int half = 0; half < 2; half++) {
            const int t = bt * 128 + wr * 64 + mi * 16 + g0 + half * 8;
            const float g = g_gate[bh * Tdim + t];
            const float bco = g * ssc * __expf(-0.05f * (float)t);
            float* rowp = Sbase + (size_t)t * Tdim;
            __half* hrow = Shb + (size_t)t * Tdim;
#pragma unroll
            for (int ni = 0; ni < 8; ni++) {
                const int ss = bs * 128 + wc * 64 + ni * 8 + tg * 2;
                const float e0 = __expf(0.05f * (float)ss);
                float v0 = acc[mi][ni][half * 2 + 0];
                float v1 = acc[mi][ni][half * 2 + 1];
                float2 o;
                o.x = (t > ss)     ? v0 * fmaf(bco, e0, g) : 0.f;
                o.y = (t > ss + 1) ? v1 * fmaf(bco, e0 * 1.0512710963760241f, g)
                                   : 0.f;
                *(float2*)(rowp + ss) = o;
                __half2 h;
                h.x = __float2half(o.x);
                h.y = __float2half(o.y);
                *(__half2*)(hrow + ss) = h;
            }
        }
    }
}

// ===========================================================================
// GEMM2: 64x128 tile, 4 warps (1x4), warp 64x32, 256 CTAs for balance.
// Stage = A(8K)+B(16K) = 24KB; 3 stages = 72KB; 2 CTAs/SM.
// ===========================================================================
#define STG_OUT 24576
#define SMEM_OUT (3 * STG_OUT)

__global__ __launch_bounds__(128, 2) void out_tc_kernel(float* __restrict__ Out) {
    extern __shared__ char smem[];
    const int bh = blockIdx.z;
    const int b = bh / NHdim;
    const int bt = blockIdx.y;   // 0..15, 64-row block
    const int bd = blockIdx.x;   // 0..1, 128-col block

    const uint32_t sbase = smem_u32(smem);
    const int tid = threadIdx.x;
    const int wid = tid >> 5;   // 0..3 -> n block
    const int lid = tid & 31;

    // Fragment offsets: warp tile 64x32 of a 64-row A and 128-row B stage.
    uint32_t a_off[4], b_off[2];
    {
        const int a_row = (lid & 15);
        const int a_kb = (lid >> 4) * 16;
#pragma unroll
        for (int mi = 0; mi < 4; mi++)
            a_off[mi] = swz((a_row + mi * 16) * 128 + a_kb);
        const int b_row = wid * 32 + (lid & 7) + ((lid >> 4) << 3);
        const int b_kb = ((lid >> 3) & 1) * 16;
#pragma unroll
        for (int nb = 0; nb < 2; nb++)
            b_off[nb] = swz((b_row + nb * 16) * 128 + b_kb);
    }
    // Load lines: A 4/thread (row=tid>>1), B 8/thread (rows tid>>3 + 16j).
    uint32_t swA[4], goA[4], swB[8], goB[8];
    {
        const int arow = tid >> 1;
        const int acb = (tid & 1) * 16;
#pragma unroll
        for (int j = 0; j < 4; j++) {
            swA[j] = swz(arow * 128 + acb + j * 32);
            goA[j] = (uint32_t)arow * (Tdim * 2) + acb + j * 32;
        }
        const int brow = tid >> 3;
        const int bcb = (tid & 7) * 16;
#pragma unroll
        for (int j = 0; j < 8; j++) {
            swB[j] = swz((brow + 16 * j) * 128 + bcb);
            goB[j] = (uint32_t)(brow + 16 * j) * (Tdim * 2) + bcb;
        }
    }

    const char* Ahb = (const char*)(g_Sh + ((size_t)bh * Tdim + bt * 64) * Tdim);
    const char* Bhb = (const char*)(g_VTh + ((size_t)b * Ddim + bd * 128) * Tdim);

    float acc[4][4][4];
#pragma unroll
    for (int i = 0; i < 4; i++)
#pragma unroll
        for (int j = 0; j < 4; j++)
#pragma unroll
            for (int k = 0; k < 4; k++) acc[i][j][k] = 0.f;

    const int NCH = bt + 1;  // causal: K up to (bt+1)*64
#pragma unroll
    for (int c = 0; c < 2; c++) {
        if (c < NCH) {
            uint32_t s0 = sbase + c * STG_OUT;
            size_t kb = (size_t)c * 128;
#pragma unroll
            for (int j = 0; j < 4; j++) cp16(s0 + swA[j], Ahb + goA[j] + kb);
#pragma unroll
            for (int j = 0; j < 8; j++)
                cp16(s0 + 8192 + swB[j], Bhb + goB[j] + kb);
        }
        asm volatile("cp.async.commit_group;" ::: "memory");
    }

    int st = 0, stp = 2;
    for (int i = 0; i < NCH; i++) {
        asm volatile("cp.async.wait_group 1;" ::: "memory");
        __syncthreads();
        const uint32_t s0 = sbase + st * STG_OUT;
        const uint32_t bsm = s0 + 8192;
        const bool pf = (i + 2 < NCH);
        const uint32_t sp = sbase + stp * STG_OUT;
        const size_t kb = (size_t)(i + 2) * 128;
#pragma unroll
        for (int ks = 0; ks < 4; ks++) {
            if (pf) {  // 3 of 12 lines per ks step
                cp16(sp + swA[ks], Ahb + goA[ks] + kb);
                cp16(sp + 8192 + swB[2 * ks],     Bhb + goB[2 * ks] + kb);
                cp16(sp + 8192 + swB[2 * ks + 1], Bhb + goB[2 * ks + 1] + kb);
            }
            const uint32_t kx = ks * 32;
            uint32_t b0[4], b1[4];
            ldm_x4(b0, bsm + (b_off[0] ^ kx));
            ldm_x4(b1, bsm + (b_off[1] ^ kx));
            uint32_t a0[4], a1[4];
            ldm_x4(a0, s0 + (a_off[0] ^ kx));
            ldm_x4(a1, s0 + (a_off[1] ^ kx));
            mma16816(acc[0][0], a0, b0[0], b0[1]);
            mma16816(acc[0][1], a0, b0[2], b0[3]);
            mma16816(acc[0][2], a0, b1[0], b1[1]);
            mma16816(acc[0][3], a0, b1[2], b1[3]);
            ldm_x4(a0, s0 + (a_off[2] ^ kx));
            mma16816(acc[1][0], a1, b0[0], b0[1]);
            mma16816(acc[1][1], a1, b0[2], b0[3]);
            mma16816(acc[1][2], a1, b1[0], b1[1]);
            mma16816(acc[1][3], a1, b1[2], b1[3]);
            ldm_x4(a1, s0 + (a_off[3] ^ kx));
            mma16816(acc[2][0], a0, b0[0], b0[1]);
            mma16816(acc[2][1], a0, b0[2], b0[3]);
            mma16816(acc[2][2], a0, b1[0], b1[1]);
            mma16816(acc[2][3], a0, b1[2], b1[3]);
            mma16816(acc[3][0], a1, b0[0], b0[1]);
            mma16816(acc[3][1], a1, b0[2], b0[3]);
            mma16816(acc[3][2], a1, b1[0], b1[1]);
            mma16816(acc[3][3], a1, b1[2], b1[3]);
        }
        asm volatile("cp.async.commit_group;" ::: "memory");
        st = (st == 2) ? 0 : st + 1;
        stp = (stp == 2) ? 0 : stp + 1;
    }

    const int g0 = lid >> 2;
    const int tg = lid & 3;
#pragma unroll
    for (int mi = 0; mi < 4; mi++) {
#pragma unroll
        for (int half = 0; half < 2; half++) {
            const int t = bt * 64 + mi * 16 + g0 + half * 8;
            float* rowp = Out + ((size_t)bh * Tdim + t) * Ddim;
#pragma unroll
            for (int ni = 0; ni < 4; ni++) {
                const int d = bd * 128 + wid * 32 + ni * 8 + tg * 2;
                float2 o;
                o.x = acc[mi][ni][half * 2 + 0];
                o.y = acc[mi][ni][half * 2 + 1];
                *(float2*)(rowp + d) = o;
            }
        }
    }
}

// ---------------------------------------------------------------------------
extern "C" void kernel_launch(void* const* d_in, const int* in_sizes, int n_in,
                              void* d_out, int out_size) {
    const float* Q      = (const float*)d_in[0];
    const float* V      = (const float*)d_in[1];
    const float* traces = (const float*)d_in[2];
    const float* scale  = (const float*)d_in[3];
    float* out = (float*)d_out;

    const size_t OUT_ELEMS = (size_t)BHdim * Tdim * Ddim;
    const size_t SC_ELEMS  = (size_t)BHdim * Tdim * Tdim;

    float* scores;
    if ((size_t)out_size >= OUT_ELEMS + SC_ELEMS) {
        scores = out + OUT_ELEMS;
    } else {
        void* p = nullptr;
        cudaGetSymbolAddress(&p, g_S_fallback);
        scores = (float*)p;
    }

    static bool attr_set = false;
    if (!attr_set) {
        cudaFuncSetAttribute(scores_tc_kernel,
                             cudaFuncAttributeMaxDynamicSharedMemorySize,
                             SMEM_SC);
        cudaFuncSetAttribute(out_tc_kernel,
                             cudaFuncAttributeMaxDynamicSharedMemorySize,
                             SMEM_OUT);
        attr_set = true;
    }

    zero_upper_kernel<<<28 * BHdim, 256>>>(scores);

    const size_t nq = (size_t)BHdim * Tdim * (Ndim / 4);
    rope_kernel<<<(unsigned)((nq + 255) / 256), 256>>>(Q);
    gate_kernel<<<BHdim * Tdim, 32>>>(traces);
    dim3 gv(Tdim / 32, Ddim / 32, Bdim);
    vt_kernel<<<gv, dim3(32, 8)>>>(V);

    scores_tc_kernel<<<36 * BHdim, 128, SMEM_SC>>>(scores, scale);

    dim3 g2(Ddim / 128, Tdim / 64, BHdim);
    out_tc_kernel<<<g2, 128, SMEM_OUT>>>(out);
}

// round 17
// speedup vs baseline: 1.0484x; 1.0484x over previous
#include <cuda_runtime.h>
#include <cuda_fp16.h>
#include <math.h>
#include <stdint.h>

#define Bdim 2
#define NHdim 4
#define Tdim 1024
#define Ndim 8192
#define Ddim 256
#define BHdim (Bdim * NHdim)

// Scratch (no cudaMalloc allowed)
static __device__ __half g_Qh[67108864];  // [BH, T, N] rope(Q) fp16, 128 MB
static __device__ __half g_Sh[8388608];   // [BH, T, T] scores fp16
static __device__ __half g_VTh[Bdim * Ddim * Tdim];  // [B, D, T] V^T fp16
static __device__ float g_gate[BHdim * Tdim];
static __device__ float g_S_fallback[8388608];

// ---------------------------------------------------------------------------
// PTX helpers
// ---------------------------------------------------------------------------
__device__ __forceinline__ uint32_t smem_u32(const void* p) {
    uint32_t a;
    asm("{ .reg .u64 t; cvta.to.shared.u64 t, %1; cvt.u32.u64 %0, t; }"
        : "=r"(a) : "l"(p));
    return a;
}
__device__ __forceinline__ void cp16(uint32_t s, const void* g) {
    asm volatile("cp.async.cg.shared.global [%0], [%1], 16;" :: "r"(s), "l"(g)
                 : "memory");
}
__device__ __forceinline__ void ldm_x4(uint32_t* r, uint32_t addr) {
    asm volatile(
        "ldmatrix.sync.aligned.m8n8.x4.shared.b16 {%0,%1,%2,%3}, [%4];"
        : "=r"(r[0]), "=r"(r[1]), "=r"(r[2]), "=r"(r[3]) : "r"(addr));
}
__device__ __forceinline__ void mma16816(float* c, const uint32_t* a,
                                         uint32_t b0, uint32_t b1) {
    asm volatile(
        "mma.sync.aligned.m16n8k16.row.col.f32.f16.f16.f32 "
        "{%0,%1,%2,%3}, {%4,%5,%6,%7}, {%8,%9}, {%0,%1,%2,%3};"
        : "+f"(c[0]), "+f"(c[1]), "+f"(c[2]), "+f"(c[3])
        : "r"(a[0]), "r"(a[1]), "r"(a[2]), "r"(a[3]), "r"(b0), "r"(b1));
}
__device__ __forceinline__ uint32_t swz(uint32_t off) {
    return off ^ ((off >> 3) & 0x70);  // SW128
}
__device__ __forceinline__ void mbar_init(uint32_t a, uint32_t cnt) {
    asm volatile("mbarrier.init.shared.b64 [%0], %1;" :: "r"(a), "r"(cnt)
                 : "memory");
}
__device__ __forceinline__ void mbar_wait(uint32_t a, uint32_t parity) {
    asm volatile(
        "{\n\t.reg .pred P;\n"
        "WL_%=:\n\t"
        "mbarrier.try_wait.parity.acquire.cta.shared::cta.b64 P, [%0], %1, 0x989680;\n\t"
        "@!P bra WL_%=;\n\t}"
        :: "r"(a), "r"(parity) : "memory");
}
__device__ __forceinline__ void mbar_arrive(uint32_t a) {
    asm volatile("mbarrier.arrive.shared.b64 _, [%0];" :: "r"(a) : "memory");
}
__device__ __forceinline__ void cp_arrive(uint32_t a) {
    asm volatile("cp.async.mbarrier.arrive.noinc.shared.b64 [%0];" :: "r"(a)
                 : "memory");
}

// ---------------------------------------------------------------------------
// RoPE -> fp16
// ---------------------------------------------------------------------------
__global__ void rope_kernel(const float* __restrict__ Q) {
    size_t idx = (size_t)blockIdx.x * blockDim.x + threadIdx.x;
    const size_t NQ = (size_t)BHdim * Tdim * (Ndim / 4);
    if (idx >= NQ) return;
    int p2 = (int)(idx % (Ndim / 4));
    int t = (int)((idx / (Ndim / 4)) % Tdim);
    float4 v = ((const float4*)Q)[idx];
    const float tf = (float)t;
    const float k = -16.0f * 2.0f / (float)Ndim;

    float fr0 = exp2f(k * (float)(2 * p2)) * 0.15915494309189535f;
    float ph0 = tf * fr0;
    ph0 = (ph0 - floorf(ph0)) * 6.283185307179586f;
    float s0, c0;
    __sincosf(ph0, &s0, &c0);

    float fr1 = exp2f(k * (float)(2 * p2 + 1)) * 0.15915494309189535f;
    float ph1 = tf * fr1;
    ph1 = (ph1 - floorf(ph1)) * 6.283185307179586f;
    float s1, c1;
    __sincosf(ph1, &s1, &c1);

    __half2 h0, h1;
    h0.x = __float2half(v.x * c0 - v.y * s0);
    h0.y = __float2half(v.y * c0 + v.x * s0);
    h1.x = __float2half(v.z * c1 - v.w * s1);
    h1.y = __float2half(v.w * c1 + v.z * s1);
    ((__half2*)g_Qh)[idx * 2 + 0] = h0;
    ((__half2*)g_Qh)[idx * 2 + 1] = h1;
}

// ---------------------------------------------------------------------------
// Fused prep: [0,512) vt | [512,1536) gate | [1536,1760) zero-upper.
// Single stream, capture-safe.
// ---------------------------------------------------------------------------
#define PREP_VT 512
#define PREP_GATE 1024
#define PREP_ZERO 224
#define PREP_BLOCKS (PREP_VT + PREP_GATE + PREP_ZERO)

__global__ void prep_kernel(const float* __restrict__ V,
                            const float* __restrict__ traces,
                            float* __restrict__ Sc) {
    const int blk = blockIdx.x;
    if (blk < PREP_VT) {
        // ---- V transpose -> fp16: VT[b][d][s]. 32x32 tile per CTA.
        __shared__ float tile[32][33];
        const int b = blk >> 8;            // 0..1
        const int ti = blk & 255;
        const int s0 = (ti & 31) * 32;
        const int d0 = (ti >> 5) * 32;
        const int tx = threadIdx.x & 31;
        const int ty = threadIdx.x >> 5;   // 0..7
#pragma unroll
        for (int j = 0; j < 4; j++)
            tile[ty + 8 * j][tx] =
                V[(size_t)b * Tdim * Ddim + (size_t)(s0 + ty + 8 * j) * Ddim +
                  d0 + tx];
        __syncthreads();
#pragma unroll
        for (int j = 0; j < 4; j++) {
            int d = d0 + ty + 8 * j;
            int s = s0 + tx;
            float v = tile[tx][ty + 8 * j];
            g_VTh[(size_t)b * Ddim * Tdim + (size_t)d * Tdim + s] =
                __float2half(v);
        }
    } else if (blk < PREP_VT + PREP_GATE) {
        // ---- Gate: 8 rows per CTA (one per warp).
        const int row = (blk - PREP_VT) * 8 + (threadIdx.x >> 5);
        const int lid = threadIdx.x & 31;
        const float* pr = traces + (size_t)row * Ddim;
        float sum = 0.f;
#pragma unroll
        for (int i = 0; i < 8; i++) sum += pr[lid + 32 * i];
#pragma unroll
        for (int o = 16; o; o >>= 1) sum += __shfl_xor_sync(0xffffffffu, sum, o);
        if (lid == 0) {
            float m = sum * (1.0f / (float)Ddim);
            float sig = 1.0f / (1.0f + expf(-m));
            g_gate[row] = 0.5f + 0.5f * sig;
        }
    } else {
        // ---- Zero strictly-upper tiles (bt < bs).
        const int idx = blk - PREP_VT - PREP_GATE;  // 0..223
        const int bh = idx & 7;
        int j = idx >> 3;  // 0..27
        int c = (int)((sqrtf(8.f * (float)j + 1.f) + 1.f) * 0.5f);
        while (c * (c - 1) / 2 > j) c--;
        while ((c + 1) * c / 2 <= j) c++;
        const int bs = c;
        const int bt = j - c * (c - 1) / 2;
        float* Sbase = Sc + (size_t)bh * Tdim * Tdim;
        __half* Shb = g_Sh + (size_t)bh * Tdim * Tdim;
        const int r0 = bt * 128, c0 = bs * 128;
        float4 z = make_float4(0.f, 0.f, 0.f, 0.f);
        for (int i = threadIdx.x; i < 128 * 32; i += 256) {
            int r = i >> 5, cc = (i & 31) << 2;
            *(float4*)(Sbase + (size_t)(r0 + r) * Tdim + c0 + cc) = z;
        }
        for (int i = threadIdx.x; i < 128 * 16; i += 256) {
            int r = i >> 4, cc = (i & 15) << 3;
            *(uint4*)(Shb + (size_t)(r0 + r) * Tdim + c0 + cc) =
                make_uint4(0, 0, 0, 0);
        }
    }
}

// ===========================================================================
// SCORES: round-14 mbarrier version.
// ===========================================================================
#define STG_SC 32768
#define MB_OFF (3 * STG_SC)
#define SMEM_SC (3 * STG_SC + 64)

struct Frag4 {
    uint32_t a_off[4];
    uint32_t b_off[4];
    uint32_t sw[8];
    uint32_t gof[8];
};

__device__ __forceinline__ void frag4_setup(Frag4& f, int tid, uint32_t rstride) {
    const int lid = tid & 31;
    const int wid = tid >> 5;
    const int wr = wid >> 1;
    const int wc = wid & 1;
    const int a_row = wr * 64 + (lid & 15);
    const int a_kb = (lid >> 4) * 16;
#pragma unroll
    for (int mi = 0; mi < 4; mi++)
        f.a_off[mi] = swz((a_row + mi * 16) * 128 + a_kb);
    const int b_row = wc * 64 + (lid & 7) + ((lid >> 4) << 3);
    const int b_kb = ((lid >> 3) & 1) * 16;
#pragma unroll
    for (int nb = 0; nb < 4; nb++)
        f.b_off[nb] = swz((b_row + nb * 16) * 128 + b_kb);
    const int rbase = tid >> 3;
    const int colb = (tid & 7) * 16;
#pragma unroll
    for (int r = 0; r < 8; r++) {
        int row = rbase + 16 * r;
        f.sw[r] = swz(row * 128 + colb);
        f.gof[r] = (uint32_t)row * rstride + colb;
    }
}

__device__ __forceinline__ void ks4_step(const Frag4& f, uint32_t asm_,
                                         uint32_t bsm, uint32_t kx,
                                         float acc[4][8][4]) {
    uint32_t b[4][4];
#pragma unroll
    for (int nb = 0; nb < 4; nb++) ldm_x4(b[nb], bsm + (f.b_off[nb] ^ kx));
    uint32_t a0[4], a1[4];
    ldm_x4(a0, asm_ + (f.a_off[0] ^ kx));
    ldm_x4(a1, asm_ + (f.a_off[1] ^ kx));
#pragma unroll
    for (int nb = 0; nb < 4; nb++) {
        mma16816(acc[0][2 * nb + 0], a0, b[nb][0], b[nb][1]);
        mma16816(acc[0][2 * nb + 1], a0, b[nb][2], b[nb][3]);
    }
    ldm_x4(a0, asm_ + (f.a_off[2] ^ kx));
#pragma unroll
    for (int nb = 0; nb < 4; nb++) {
        mma16816(acc[1][2 * nb + 0], a1, b[nb][0], b[nb][1]);
        mma16816(acc[1][2 * nb + 1], a1, b[nb][2], b[nb][3]);
    }
    ldm_x4(a1, asm_ + (f.a_off[3] ^ kx));
#pragma unroll
    for (int nb = 0; nb < 4; nb++) {
        mma16816(acc[2][2 * nb + 0], a0, b[nb][0], b[nb][1]);
        mma16816(acc[2][2 * nb + 1], a0, b[nb][2], b[nb][3]);
    }
#pragma unroll
    for (int nb = 0; nb < 4; nb++) {
        mma16816(acc[3][2 * nb + 0], a1, b[nb][0], b[nb][1]);
        mma16816(acc[3][2 * nb + 1], a1, b[nb][2], b[nb][3]);
    }
}

__global__ __launch_bounds__(128, 2) void scores_tc_kernel(
    float* __restrict__ Sc, const float* __restrict__ stdp_scale) {
    extern __shared__ char smem[];
    const int bh = blockIdx.x & 7;
    int kidx = blockIdx.x >> 3;
    int bt = (int)((sqrtf(8.f * (float)kidx + 1.f) - 1.f) * 0.5f);
    while (bt * (bt + 1) / 2 > kidx) bt--;
    while ((bt + 1) * (bt + 2) / 2 <= kidx) bt++;
    const int bs = kidx - bt * (bt + 1) / 2;

    float* Sbase = Sc + (size_t)bh * Tdim * Tdim;
    __half* Shb = g_Sh + (size_t)bh * Tdim * Tdim;

    const uint32_t sbase = smem_u32(smem);
    const int tid = threadIdx.x;
    const int wid = tid >> 5;
    const int lid = tid & 31;
    const int wr = wid >> 1;
    const int wc = wid & 1;

    const uint32_t MB = sbase + MB_OFF;
    if (tid == 0) {
#pragma unroll
        for (int s = 0; s < 3; s++) {
            mbar_init(MB + s * 8, 128);
            mbar_init(MB + 24 + s * 8, 4);
        }
    }
    __syncthreads();

    Frag4 f;
    frag4_setup(f, tid, (uint32_t)Ndim * 2);

    const char* Ab = (const char*)(g_Qh + ((size_t)bh * Tdim + bt * 128) * Ndim);
    const char* Bb = (const char*)(g_Qh + ((size_t)bh * Tdim + bs * 128) * Ndim);

    float acc[4][8][4];
#pragma unroll
    for (int i = 0; i < 4; i++)
#pragma unroll
        for (int j = 0; j < 8; j++)
#pragma unroll
            for (int k = 0; k < 4; k++) acc[i][j][k] = 0.f;

    const int NCH = 128;
#pragma unroll
    for (int c = 0; c < 2; c++) {
        uint32_t s0 = sbase + c * STG_SC;
        size_t kb = (size_t)c * 128;
#pragma unroll
        for (int r = 0; r < 8; r++) {
            cp16(s0 + f.sw[r],         Ab + f.gof[r] + kb);
            cp16(s0 + 16384 + f.sw[r], Bb + f.gof[r] + kb);
        }
        cp_arrive(MB + c * 8);
    }

    int s = 0, m = 0;
    for (int c = 0; c < NCH; c++) {
        mbar_wait(MB + s * 8, m & 1);
        const uint32_t s0 = sbase + s * STG_SC;
        ks4_step(f, s0, s0 + 16384, 0, acc);

        const int p = c + 2;
        if (p < NCH) {
            int sp = s + 2;
            if (sp >= 3) sp -= 3;
            const int pdiv = m + (s >= 1 ? 1 : 0);
            if (p >= 3) mbar_wait(MB + 24 + sp * 8, (pdiv - 1) & 1);
            const uint32_t spb = sbase + sp * STG_SC;
            const size_t kb = (size_t)p * 128;
            cp16(spb + f.sw[0],         Ab + f.gof[0] + kb);
            cp16(spb + f.sw[1],         Ab + f.gof[1] + kb);
            cp16(spb + f.sw[2],         Ab + f.gof[2] + kb);
            cp16(spb + 16384 + f.sw[0], Bb + f.gof[0] + kb);
            cp16(spb + 16384 + f.sw[1], Bb + f.gof[1] + kb);
            cp16(spb + 16384 + f.sw[2], Bb + f.gof[2] + kb);
            ks4_step(f, s0, s0 + 16384, 32, acc);
            cp16(spb + f.sw[3],         Ab + f.gof[3] + kb);
            cp16(spb + f.sw[4],         Ab + f.gof[4] + kb);
            cp16(spb + f.sw[5],         Ab + f.gof[5] + kb);
            cp16(spb + 16384 + f.sw[3], Bb + f.gof[3] + kb);
            cp16(spb + 16384 + f.sw[4], Bb + f.gof[4] + kb);
            cp16(spb + 16384 + f.sw[5], Bb + f.gof[5] + kb);
            ks4_step(f, s0, s0 + 16384, 64, acc);
            cp16(spb + f.sw[6],         Ab + f.gof[6] + kb);
            cp16(spb + f.sw[7],         Ab + f.gof[7] + kb);
            cp16(spb + 16384 + f.sw[6], Bb + f.gof[6] + kb);
            cp16(spb + 16384 + f.sw[7], Bb + f.gof[7] + kb);
            cp_arrive(MB + sp * 8);
            ks4_step(f, s0, s0 + 16384, 96, acc);
        } else {
            ks4_step(f, s0, s0 + 16384, 32, acc);
            ks4_step(f, s0, s0 + 16384, 64, acc);
            ks4_step(f, s0, s0 + 16384, 96, acc);
        }
        __syncwarp();
        if (lid == 0) mbar_arrive(MB + 24 + s * 8);
        if (++s == 3) { s = 0; m++; }
    }

    const float ssc = stdp_scale[0] * 0.01f;
    const int g0 = lid >> 2;
    const int tg = lid & 3;
#pragma unroll
    for (int mi = 0; mi < 4; mi++) {
#pragma unroll
        for (int half = 0; half < 2; half++) {
            const int t = bt * 128 + wr * 64 + mi * 16 + g0 + half * 8;
            const float g = g_gate[bh * Tdim + t];
            const float bco = g * ssc * __expf(-0.05f * (float)t);
            float* rowp = Sbase + (size_t)t * Tdim;
            __half* hrow = Shb + (size_t)t * Tdim;
#pragma unroll
            for (int ni = 0; ni < 8; ni++) {
                const int ss = bs * 128 + wc * 64 + ni * 8 + tg * 2;
                const float e0 = __expf(0.05f * (float)ss);
                float v0 = acc[mi][ni][half * 2 + 0];
                float v1 = acc[mi][ni][half * 2 + 1];
                float2 o;
                o.x = (t > ss)     ? v0 * fmaf(bco, e0, g) : 0.f;
                o.y = (t > ss + 1) ? v1 * fmaf(bco, e0 * 1.0512710963760241f, g)
                                   : 0.f;
                *(float2*)(rowp + ss) = o;
                __half2 h;
                h.x = __float2half(o.x);
                h.y = __float2half(o.y);
                *(__half2*)(hrow + ss) = h;
            }
        }
    }
}

// ===========================================================================
// GEMM2: round-14 version — 8 warps 2x4, warp 64x32, 128x128 tile.
// ===========================================================================
struct FragCtx {
    uint32_t a_off[4];
    uint32_t b_off[2];
    uint32_t sw[4];
    int row[4];
    int colb;
};

__device__ __forceinline__ void frag_setup(FragCtx& f, int tid) {
    const int lid = tid & 31;
    const int wid = tid >> 5;
    const int wr = wid >> 2;
    const int wc = wid & 3;
    const int a_row = wr * 64 + (lid & 15);
    const int a_kb = (lid >> 4) * 16;
#pragma unroll
    for (int mi = 0; mi < 4; mi++)
        f.a_off[mi] = swz((a_row + mi * 16) * 128 + a_kb);
    const int b_row = wc * 32 + (lid & 7) + ((lid >> 4) << 3);
    const int b_kb = ((lid >> 3) & 1) * 16;
#pragma unroll
    for (int nb = 0; nb < 2; nb++)
        f.b_off[nb] = swz((b_row + nb * 16) * 128 + b_kb);
    const int rbase = tid >> 3;
    f.colb = (tid & 7) * 16;
#pragma unroll
    for (int r = 0; r < 4; r++) {
        f.row[r] = rbase + 32 * r;
        f.sw[r] = swz(f.row[r] * 128 + f.colb);
    }
}

__device__ __forceinline__ void ks_step(const FragCtx& f, uint32_t s0,
                                        uint32_t bsm, uint32_t kx,
                                        float acc[4][4][4]) {
    uint32_t b0[4], b1[4];
    ldm_x4(b0, bsm + (f.b_off[0] ^ kx));
    ldm_x4(b1, bsm + (f.b_off[1] ^ kx));
    uint32_t a0[4], a1[4];
    ldm_x4(a0, s0 + (f.a_off[0] ^ kx));
    ldm_x4(a1, s0 + (f.a_off[1] ^ kx));
    mma16816(acc[0][0], a0, b0[0], b0[1]);
    mma16816(acc[0][1], a0, b0[2], b0[3]);
    mma16816(acc[0][2], a0, b1[0], b1[1]);
    mma16816(acc[0][3], a0, b1[2], b1[3]);
    ldm_x4(a0, s0 + (f.a_off[2] ^ kx));
    mma16816(acc[1][0], a1, b0[0], b0[1]);
    mma16816(acc[1][1], a1, b0[2], b0[3]);
    mma16816(acc[1][2], a1, b1[0], b1[1]);
    mma16816(acc[1][3], a1, b1[2], b1[3]);
    ldm_x4(a1, s0 + (f.a_off[3] ^ kx));
    mma16816(acc[2][0], a0, b0[0], b0[1]);
    mma16816(acc[2][1], a0, b0[2], b0[3]);
    mma16816(acc[2][2], a0, b1[0], b1[1]);
    mma16816(acc[2][3], a0, b1[2], b1[3]);
    mma16816(acc[3][0], a1, b0[0], b0[1]);
    mma16816(acc[3][1], a1, b0[2], b0[3]);
    mma16816(acc[3][2], a1, b1[0], b1[1]);
    mma16816(acc[3][3], a1, b1[2], b1[3]);
}

#define STG_OUT 32768
#define SMEM_OUT (3 * STG_OUT)

__global__ __launch_bounds__(256, 2) void out_tc_kernel(float* __restrict__ Out) {
    extern __shared__ char smem[];
    const int bh = blockIdx.z;
    const int b = bh / NHdim;
    const int bt = blockIdx.y;
    const int bd = blockIdx.x;

    const uint32_t sbase = smem_u32(smem);
    const int tid = threadIdx.x;
    const int wid = tid >> 5;
    const int lid = tid & 31;
    const int wr = wid >> 2;
    const int wc = wid & 3;

    FragCtx f;
    frag_setup(f, tid);

    const size_t rs = (size_t)Tdim * 2;
    const char* Ahb = (const char*)(g_Sh + ((size_t)bh * Tdim + bt * 128) * Tdim);
    const char* Bhb = (const char*)(g_VTh + ((size_t)b * Ddim + bd * 128) * Tdim);
    const char* pA[4];
    const char* pB[4];
#pragma unroll
    for (int r = 0; r < 4; r++) {
        pA[r] = Ahb + (size_t)f.row[r] * rs + f.colb;
        pB[r] = Bhb + (size_t)f.row[r] * rs + f.colb;
    }

    float acc[4][4][4];
#pragma unroll
    for (int i = 0; i < 4; i++)
#pragma unroll
        for (int j = 0; j < 4; j++)
#pragma unroll
            for (int k = 0; k < 4; k++) acc[i][j][k] = 0.f;

    const int NCH = (bt + 1) * 2;
#pragma unroll
    for (int c = 0; c < 2; c++) {
        uint32_t s0 = sbase + c * STG_OUT;
        size_t kb = (size_t)c * 128;
#pragma unroll
        for (int r = 0; r < 4; r++) {
            cp16(s0 + f.sw[r],         pA[r] + kb);
            cp16(s0 + 16384 + f.sw[r], pB[r] + kb);
        }
        asm volatile("cp.async.commit_group;" ::: "memory");
    }

    int st = 0, stp = 2;
    for (int i = 0; i < NCH; i++) {
        asm volatile("cp.async.wait_group 1;" ::: "memory");
        __syncthreads();
        const uint32_t s0 = sbase + st * STG_OUT;
        const bool pf = (i + 2 < NCH);
        const uint32_t sp = sbase + stp * STG_OUT;
        const size_t kb = (size_t)(i + 2) * 128;
#pragma unroll
        for (int ks = 0; ks < 4; ks++) {
            if (pf) {
                cp16(sp + f.sw[ks],         pA[ks] + kb);
                cp16(sp + 16384 + f.sw[ks], pB[ks] + kb);
            }
            ks_step(f, s0, s0 + 16384, ks * 32, acc);
        }
        asm volatile("cp.async.commit_group;" ::: "memory");
        st = (st == 2) ? 0 : st + 1;
        stp = (stp == 2) ? 0 : stp + 1;
    }

    const int g0 = lid >> 2;
    const int tg = lid & 3;
#pragma unroll
    for (int mi = 0; mi < 4; mi++) {
#pragma unroll
        for (int half = 0; half < 2; half++) {
            const int t = bt * 128 + wr * 64 + mi * 16 + g0 + half * 8;
            float* rowp = Out + ((size_t)bh * Tdim + t) * Ddim;
#pragma unroll
            for (int ni = 0; ni < 4; ni++) {
                const int d = bd * 128 + wc * 32 + ni * 8 + tg * 2;
                float2 o;
                o.x = acc[mi][ni][half * 2 + 0];
                o.y = acc[mi][ni][half * 2 + 1];
                *(float2*)(rowp + d) = o;
            }
        }
    }
}

// ---------------------------------------------------------------------------
extern "C" void kernel_launch(void* const* d_in, const int* in_sizes, int n_in,
                              void* d_out, int out_size) {
    const float* Q      = (const float*)d_in[0];
    const float* V      = (const float*)d_in[1];
    const float* traces = (const float*)d_in[2];
    const float* scale  = (const float*)d_in[3];
    float* out = (float*)d_out;

    const size_t OUT_ELEMS = (size_t)BHdim * Tdim * Ddim;
    const size_t SC_ELEMS  = (size_t)BHdim * Tdim * Tdim;

    float* scores;
    if ((size_t)out_size >= OUT_ELEMS + SC_ELEMS) {
        scores = out + OUT_ELEMS;
    } else {
        void* p = nullptr;
        cudaGetSymbolAddress(&p, g_S_fallback);
        scores = (float*)p;
    }

    static bool attr_set = false;
    if (!attr_set) {
        cudaFuncSetAttribute(scores_tc_kernel,
                             cudaFuncAttributeMaxDynamicSharedMemorySize,
                             SMEM_SC);
        cudaFuncSetAttribute(out_tc_kernel,
                             cudaFuncAttributeMaxDynamicSharedMemorySize,
                             SMEM_OUT);
        attr_set = true;
    }

    // Single stream, capture-safe.
    prep_kernel<<<PREP_BLOCKS, 256>>>(V, traces, scores);

    const size_t nq = (size_t)BHdim * Tdim * (Ndim / 4);
    rope_kernel<<<(unsigned)((nq + 255) / 256), 256>>>(Q);

    scores_tc_kernel<<<36 * BHdim, 128, SMEM_SC>>>(scores, scale);

    dim3 g2(Ddim / 128, Tdim / 128, BHdim);
    out_tc_kernel<<<g2, 256, SMEM_OUT>>>(out);
}